// round 14
// baseline (speedup 1.0000x reference)
#include <cuda_runtime.h>
#include <cuda_fp16.h>
#include <math.h>
#include <cstdint>

// Problem constants
constexpr int B = 8;
constexpr int T = 4096;
constexpr int C = 8;
constexpr int E = 1024;   // MAX_EVENTS
constexpr int D = 512;
constexpr int F = 2048;
constexpr int NL = 4;
constexpr int NH = 8;
constexpr int DH = 64;

// sigma16 k-permutation (within 16-groups): p16(j) = ((j&7)>>1)*4 + (j&1) + ((j>>3)&1)*2
// => fp16 m16n8k16 fragment k-set {2q,2q+1,2q+8,2q+9} is contiguous (one LDS.64).

// ---------------- device scratch (no allocation allowed) ----------------
__device__ float g_rows[B * E * 11];
__device__ float g_mask[B * E];
__device__ float g_h[(size_t)B * E * D];
__device__ float g_pool[B * 16 * D];              // LN+pool partials
__device__ float g_pcnt[B * 16];
// fp16 planes
__device__ __half g_qh[(size_t)B * E * D];        // sigma16 on dh
__device__ __half g_kh[(size_t)B * E * D];        // sigma16 on dh
__device__ __half g_vh[(size_t)B * E * D];        // plain
__device__ __half g_zh[(size_t)B * E * D];
__device__ __half g_oh[(size_t)B * E * D];
__device__ __half g_fh[(size_t)B * E * F];
__device__ __half g_wH[12582912];

constexpr size_t OFF_QKV = 0;                    // 4 * 3*D*D
constexpr size_t OFF_OT  = 3145728;              // 4 * D*D
constexpr size_t OFF_W1T = 4194304;              // 4 * D*F
constexpr size_t OFF_W2T = 8388608;              // 4 * F*D

// ================= PTX helpers =================
__device__ __forceinline__ uint32_t smem_u32(const void* p) {
    uint32_t a;
    asm("{ .reg .u64 t; cvta.to.shared.u64 t, %1; cvt.u32.u64 %0, t; }" : "=r"(a) : "l"(p));
    return a;
}
__device__ __forceinline__ void cpasync16(uint32_t dst, const void* src) {
    asm volatile("cp.async.cg.shared.global [%0], [%1], 16;" :: "r"(dst), "l"(src));
}
#define CP_COMMIT() asm volatile("cp.async.commit_group;" ::: "memory")
#define CP_WAIT(n)  asm volatile("cp.async.wait_group %0;" :: "n"(n) : "memory")

__device__ __forceinline__ void mma_fp16(float* c,
                                         uint32_t a0, uint32_t a1, uint32_t a2, uint32_t a3,
                                         uint32_t b0, uint32_t b1) {
    asm volatile(
        "mma.sync.aligned.m16n8k16.row.col.f32.f16.f16.f32 "
        "{%0,%1,%2,%3}, {%4,%5,%6,%7}, {%8,%9}, {%0,%1,%2,%3};"
        : "+f"(c[0]), "+f"(c[1]), "+f"(c[2]), "+f"(c[3])
        : "r"(a0), "r"(a1), "r"(a2), "r"(a3), "r"(b0), "r"(b1));
}
__device__ __forceinline__ void ldm4t(uint32_t& r0, uint32_t& r1, uint32_t& r2, uint32_t& r3,
                                      uint32_t addr) {
    asm volatile("ldmatrix.sync.aligned.m8n8.x4.trans.shared.b16 {%0,%1,%2,%3}, [%4];"
                 : "=r"(r0), "=r"(r1), "=r"(r2), "=r"(r3) : "r"(addr));
}

__device__ __forceinline__ void store_h2(__half* P, size_t idx, float x, float y) {
    __half2 h;
    h.x = __float2half_rn(x);
    h.y = __float2half_rn(y);
    *(__half2*)(P + idx) = h;
}

// ---------------- GELU (tanh approximation, matches jax.nn.gelu default) ----
__device__ __forceinline__ float gelu_f(float v) {
    const float c = 0.7978845608028654f;
    float t = tanhf(c * (v + 0.044715f * v * v * v));
    return 0.5f * v * (1.f + t);
}

// ================= fp16 mma.sync GEMM ========================================
// C[M,N] = A[M,K] @ W[K,N]; A and W fp16, K-major for W ([N,K]), sigma16-
// permuted on k. Block tile 128x128, BK=64 (two contiguous BK=32 sub-tiles,
// identical conflict-free 96B-stride layout), 128 threads (4 warps, 2x2 of
// 64x64 warp tiles). Double-buffered cp.async, ONE __syncthreads per K-iter.
// OUT: 0 = fp32 C0 (opt residual), 1 = fp16 sigma16 plane,
//      2 = SPLIT3 QKV (q,k fp16 sigma16 planes; v fp16 plain plane).
constexpr int SUB_B = 128 * 96;              // 12288 bytes per BK=32 sub-tile
constexpr int PLANE_B = 2 * SUB_B;           // 24576 bytes per plane (BK=64)
constexpr int BUF_B = 2 * PLANE_B;           // 49152 bytes per buffer (A+W)
constexpr int GSMEM = 2 * BUF_B;             // 98304 bytes (2 buffers)

template <int BIAS, int GELU_, int RES, int OUT>
__global__ __launch_bounds__(128)
void tgemm_kernel(const __half* __restrict__ Ah, const __half* __restrict__ Wh,
                  const float* __restrict__ bias,
                  void* __restrict__ C0v, void* __restrict__ C1v, void* __restrict__ C2v,
                  int M, int N, int K) {
    extern __shared__ char smem[];
    const uint32_t sb = smem_u32(smem);
    const int tid = threadIdx.x;
    const int wid = tid >> 5, lane = tid & 31;
    const int g = lane >> 2, q = lane & 3;
    const int wm = (wid & 1) * 64;
    const int wn = (wid >> 1) * 64;
    const int bn = blockIdx.x;
    const int n0 = bn * 128;
    const int m0 = blockIdx.y * 128;

    float acc[4][8][4];
#pragma unroll
    for (int i = 0; i < 4; i++)
#pragma unroll
        for (int j = 0; j < 8; j++)
#pragma unroll
            for (int k = 0; k < 4; k++) acc[i][j][k] = 0.f;

    // fill a BK=64 tile: per plane 1024 chunks of 16B (8 per 128B row),
    // stored as two BK=32 sub-tiles (96B row stride each).
    auto load_tile = [&](int bf, int i) {
        const int k0 = i * 64;
        const __half* gA = Ah + (size_t)m0 * K + k0;
        const __half* gW = Wh + (size_t)n0 * K + k0;
        const uint32_t base = sb + (uint32_t)bf * BUF_B;
#pragma unroll
        for (int j = 0; j < 8; j++) {
            const int ch = j * 128 + tid;          // 0..1023
            const int row = ch >> 3, c16 = ch & 7;
            const uint32_t so = (uint32_t)((c16 >> 2) * SUB_B + row * 96 + (c16 & 3) * 16);
            cpasync16(base + so, gA + (size_t)row * K + c16 * 8);
            cpasync16(base + PLANE_B + so, gW + (size_t)row * K + c16 * 8);
        }
        CP_COMMIT();
    };

    const int NK = K >> 6;
    load_tile(0, 0);
    for (int i = 0; i < NK; i++) {
        CP_WAIT(0);                           // only load(i) pending
        __syncthreads();                      // tile i visible; buf (i+1)&1 free
        if (i + 1 < NK) load_tile((i + 1) & 1, i + 1);

        const __half* sAb = reinterpret_cast<const __half*>(smem) + (i & 1) * (BUF_B / 2);

#pragma unroll
        for (int s = 0; s < 4; s++) {                  // four k16 steps per BK=64
            const __half* sA = sAb + (s >> 1) * (SUB_B / 2);
            const __half* sB = sA + PLANE_B / 2;
            const int fo = (s & 1) * 16 + q * 4;
            uint32_t af[4][4];
#pragma unroll
            for (int mt = 0; mt < 4; mt++) {
                const int r0 = wm + mt * 16 + g;
                const uint2 x0 = *(const uint2*)(sA + r0 * 48 + fo);
                const uint2 x1 = *(const uint2*)(sA + (r0 + 8) * 48 + fo);
                af[mt][0] = x0.x; af[mt][2] = x0.y;
                af[mt][1] = x1.x; af[mt][3] = x1.y;
            }
#pragma unroll
            for (int nt = 0; nt < 8; nt++) {
                const int cc = wn + nt * 8 + g;
                const uint2 bv = *(const uint2*)(sB + cc * 48 + fo);
#pragma unroll
                for (int mt = 0; mt < 4; mt++)
                    mma_fp16(acc[mt][nt], af[mt][0], af[mt][1], af[mt][2], af[mt][3],
                             bv.x, bv.y);
            }
        }
    }

    // ---------------- epilogue ----------------
    if (OUT == 2) {
        const int seg = bn >> 2;
        const int c0 = (bn & 3) * 128;
#pragma unroll
        for (int mt = 0; mt < 4; mt++) {
            const int r0 = m0 + wm + mt * 16 + g;
#pragma unroll
            for (int nt = 0; nt < 8; nt++) {
                const int cbase = c0 + wn + nt * 8;
                const float2 v0 = make_float2(acc[mt][nt][0], acc[mt][nt][1]);
                const float2 v1 = make_float2(acc[mt][nt][2], acc[mt][nt][3]);
                if (seg < 2) {   // q,k: fp16 sigma16 plane
                    __half* Ch = (seg == 0) ? (__half*)C0v : (__half*)C1v;
                    const int outc = (cbase & ~15) + q * 4 + ((cbase >> 3) & 1) * 2;
                    store_h2(Ch, (size_t)r0 * 512 + outc, v0.x, v0.y);
                    store_h2(Ch, (size_t)(r0 + 8) * 512 + outc, v1.x, v1.y);
                } else {         // v: fp16 plain plane
                    __half* Vh = (__half*)C2v;
                    const size_t i0 = (size_t)r0 * 512 + cbase + 2 * q;
                    store_h2(Vh, i0, v0.x, v0.y);
                    store_h2(Vh, i0 + (size_t)8 * 512, v1.x, v1.y);
                }
            }
        }
    } else {
#pragma unroll
        for (int mt = 0; mt < 4; mt++) {
            const int r0 = m0 + wm + mt * 16 + g;
#pragma unroll
            for (int nt = 0; nt < 8; nt++) {
                const int cbase = n0 + wn + nt * 8;
                float2 v0 = make_float2(acc[mt][nt][0], acc[mt][nt][1]);
                float2 v1 = make_float2(acc[mt][nt][2], acc[mt][nt][3]);
                if (BIAS) {
                    const float2 bb = *(const float2*)(bias + cbase + 2 * q);
                    v0.x += bb.x; v0.y += bb.y; v1.x += bb.x; v1.y += bb.y;
                }
                if (GELU_) {
                    v0.x = gelu_f(v0.x); v0.y = gelu_f(v0.y);
                    v1.x = gelu_f(v1.x); v1.y = gelu_f(v1.y);
                }
                if (OUT == 0) {
                    float* p0 = (float*)C0v + (size_t)r0 * N + cbase + 2 * q;
                    float* p1 = (float*)C0v + (size_t)(r0 + 8) * N + cbase + 2 * q;
                    if (RES) {
                        const float2 o0 = *(const float2*)p0;
                        const float2 o1 = *(const float2*)p1;
                        v0.x += o0.x; v0.y += o0.y; v1.x += o1.x; v1.y += o1.y;
                    }
                    *(float2*)p0 = v0;
                    *(float2*)p1 = v1;
                } else {   // OUT == 1: fp16 sigma16 plane
                    const int outc = (cbase & ~15) + q * 4 + ((cbase >> 3) & 1) * 2;
                    __half* Ch = (__half*)C0v;
                    store_h2(Ch, (size_t)r0 * N + outc, v0.x, v0.y);
                    store_h2(Ch, (size_t)(r0 + 8) * N + outc, v1.x, v1.y);
                }
            }
        }
    }
}

// ================= fp16 mma flash attention ==================================
// grid (E/64, NH, B), 128 threads (4 warps x 16 q-rows). 64-key K/V tiles,
// double-buffered cp.async, single __syncthreads per iter.
// QK: fp16. PV: single fp16 mma, V B-frags via ldmatrix.trans.
constexpr int AOFF_K  = 5120;     // Q at 0 (64 x 80); K 2 x 5120
constexpr int AOFF_VH = 15360;    // 2 x 4608 (64 x 72, 144B stride)
constexpr int AOFF_P  = 24576;    // 64 x 80 (sigma16 on key dim)
constexpr int AOFF_MB = (24576 + 5120) * 2;   // byte offset masks (2 x 256B)
constexpr int ASMEM = AOFF_MB + 512;          // 59904 bytes

__global__ __launch_bounds__(128)
void attn_mma_kernel(const __half* __restrict__ Qg, const __half* __restrict__ Kg,
                     const __half* __restrict__ Vg,
                     const float* __restrict__ maskb, __half* __restrict__ Oh) {
    extern __shared__ char smraw[];
    __half* sh = (__half*)smraw;
    const uint32_t sb = smem_u32(smraw);
    const int qb = blockIdx.x, hd = blockIdx.y, b = blockIdx.z;
    const int tid = threadIdx.x, wid = tid >> 5, lane = tid & 31;
    const int g = lane >> 2, q = lane & 3;
    const int wr = wid * 16;
    const int koff = ((lane >> 3) & 1) * 8 + (lane & 7);
    const int dhoff = (lane >> 4) * 8;

    auto load_kv = [&](int buf, int i) {
        const size_t gbase = ((size_t)(b * E) + i * 64) * D + hd * DH;
        const __half* Kp = Kg + gbase;
        const __half* Vp = Vg + gbase;
        const uint32_t sK = sb + (uint32_t)(AOFF_K + buf * 5120) * 2;
        const uint32_t sV = sb + (uint32_t)(AOFF_VH + buf * 4608) * 2;
#pragma unroll
        for (int j = 0; j < 4; j++) {
            const int ch = j * 128 + tid;          // 512 chunks: 64 rows x 8
            const int r = ch >> 3, c = ch & 7;
            cpasync16(sK + r * 160 + c * 16, Kp + (size_t)r * D + c * 8);
            cpasync16(sV + r * 144 + c * 16, Vp + (size_t)r * D + c * 8);
        }
        if (tid < 16)
            cpasync16(sb + AOFF_MB + buf * 256 + tid * 16,
                      maskb + b * E + i * 64 + tid * 4);
        CP_COMMIT();
    };
    load_kv(0, 0);

    // Q tile -> smem (sigma16 on dh already applied by QKV GEMM)
    const __half* Qp = Qg + ((size_t)(b * E) + qb * 64) * D + hd * DH;
#pragma unroll
    for (int j = 0; j < 4; j++) {
        const int ch = j * 128 + tid;
        const int r = ch >> 3, c = ch & 7;
        *(uint4*)(sh + r * 80 + c * 8) = *(const uint4*)(Qp + (size_t)r * D + c * 8);
    }
    __syncthreads();

    uint32_t qa[4][4];
#pragma unroll
    for (int kg = 0; kg < 4; kg++) {
        const uint2 x0 = *(const uint2*)(sh + (wr + g) * 80 + kg * 16 + q * 4);
        const uint2 x1 = *(const uint2*)(sh + (wr + g + 8) * 80 + kg * 16 + q * 4);
        qa[kg][0] = x0.x; qa[kg][2] = x0.y;
        qa[kg][1] = x1.x; qa[kg][3] = x1.y;
    }
    __syncwarp();

    float m0 = -1e30f, m1 = -1e30f, l0 = 0.f, l1 = 0.f;
    float oacc[8][4];
#pragma unroll
    for (int nf = 0; nf < 8; nf++)
#pragma unroll
        for (int k = 0; k < 4; k++) oacc[nf][k] = 0.f;

    __half* Ph0 = sh + AOFF_P + (wr + g) * 80;
    __half* Ph1 = sh + AOFF_P + (wr + g + 8) * 80;

    for (int i = 0; i < 16; i++) {
        const int buf = i & 1;
        CP_WAIT(0);                       // only load(i) pending
        __syncthreads();                  // tile i visible; buf (i+1)&1 free
        if (i + 1 < 16) load_kv((i + 1) & 1, i + 1);

        const __half* sK = sh + AOFF_K + buf * 5120;
        const uint32_t sV32 = sb + (uint32_t)(AOFF_VH + buf * 4608) * 2;
        const float* kmb = (const float*)(smraw + AOFF_MB + buf * 256);

        // ---- scores: S = Q K^T (fp16) ----
        float sc[8][4];
#pragma unroll
        for (int nf = 0; nf < 8; nf++)
#pragma unroll
            for (int k = 0; k < 4; k++) sc[nf][k] = 0.f;
#pragma unroll
        for (int kg = 0; kg < 4; kg++) {
#pragma unroll
            for (int nf = 0; nf < 8; nf++) {
                const uint2 bv = *(const uint2*)(sK + (nf * 8 + g) * 80 + kg * 16 + q * 4);
                mma_fp16(sc[nf], qa[kg][0], qa[kg][1], qa[kg][2], qa[kg][3], bv.x, bv.y);
            }
        }

        // ---- scale (1/8) + mask + online softmax ----
        float mt0 = -1e30f, mt1 = -1e30f;
#pragma unroll
        for (int nf = 0; nf < 8; nf++) {
            sc[nf][0] *= 0.125f; sc[nf][1] *= 0.125f;
            sc[nf][2] *= 0.125f; sc[nf][3] *= 0.125f;
            const float mk0 = kmb[nf * 8 + 2 * q];
            const float mk1 = kmb[nf * 8 + 2 * q + 1];
            if (mk0 == 0.f) { sc[nf][0] = -1e9f; sc[nf][2] = -1e9f; }
            if (mk1 == 0.f) { sc[nf][1] = -1e9f; sc[nf][3] = -1e9f; }
            mt0 = fmaxf(mt0, fmaxf(sc[nf][0], sc[nf][1]));
            mt1 = fmaxf(mt1, fmaxf(sc[nf][2], sc[nf][3]));
        }
        mt0 = fmaxf(mt0, __shfl_xor_sync(0xFFFFFFFFu, mt0, 1));
        mt0 = fmaxf(mt0, __shfl_xor_sync(0xFFFFFFFFu, mt0, 2));
        mt1 = fmaxf(mt1, __shfl_xor_sync(0xFFFFFFFFu, mt1, 1));
        mt1 = fmaxf(mt1, __shfl_xor_sync(0xFFFFFFFFu, mt1, 2));
        const float mn0 = fmaxf(m0, mt0), mn1 = fmaxf(m1, mt1);
        const float al0 = __expf(m0 - mn0), al1 = __expf(m1 - mn1);
        m0 = mn0; m1 = mn1;

        float ps0 = 0.f, ps1 = 0.f;
#pragma unroll
        for (int nf = 0; nf < 8; nf++) {
            const float p0 = __expf(sc[nf][0] - mn0);
            const float p1 = __expf(sc[nf][1] - mn0);
            const float p2 = __expf(sc[nf][2] - mn1);
            const float p3 = __expf(sc[nf][3] - mn1);
            ps0 += p0 + p1; ps1 += p2 + p3;
            const int pp = (nf >> 1) * 16 + q * 4 + (nf & 1) * 2;   // sigma16 pos
            store_h2(Ph0, pp, p0, p1);
            store_h2(Ph1, pp, p2, p3);
            oacc[nf][0] *= al0; oacc[nf][1] *= al0;
            oacc[nf][2] *= al1; oacc[nf][3] *= al1;
        }
        ps0 += __shfl_xor_sync(0xFFFFFFFFu, ps0, 1);
        ps0 += __shfl_xor_sync(0xFFFFFFFFu, ps0, 2);
        ps1 += __shfl_xor_sync(0xFFFFFFFFu, ps1, 1);
        ps1 += __shfl_xor_sync(0xFFFFFFFFu, ps1, 2);
        l0 = l0 * al0 + ps0; l1 = l1 * al1 + ps1;
        __syncwarp();   // P visible within warp (A-frags read only own warp rows)

        // ---- O += P V (single fp16 mma per fragment) ----
#pragma unroll
        for (int kg = 0; kg < 4; kg++) {
            const int po = kg * 16 + q * 4;
            const uint2 x0 = *(const uint2*)(Ph0 + po);
            const uint2 x1 = *(const uint2*)(Ph1 + po);
            const uint32_t rowb = (uint32_t)((kg * 16 + koff) * 144 + dhoff * 2);
#pragma unroll
            for (int nfp = 0; nfp < 4; nfp++) {
                uint32_t b0, b1, b2, b3;
                ldm4t(b0, b1, b2, b3, sV32 + rowb + nfp * 32);
                mma_fp16(oacc[2 * nfp],     x0.x, x1.x, x0.y, x1.y, b0, b1);
                mma_fp16(oacc[2 * nfp + 1], x0.x, x1.x, x0.y, x1.y, b2, b3);
            }
        }
    }

    // O -> fp16 sigma16-permuted plane (feeds WO GEMM)
    const float il0 = 1.f / l0, il1 = 1.f / l1;
    const size_t r0 = ((size_t)(b * E) + qb * 64 + wr + g) * D + hd * DH;
    const size_t r1 = r0 + (size_t)8 * D;
#pragma unroll
    for (int nf = 0; nf < 8; nf++) {
        const int outc = (nf >> 1) * 16 + q * 4 + (nf & 1) * 2;
        store_h2(Oh, r0 + outc, oacc[nf][0] * il0, oacc[nf][1] * il0);
        store_h2(Oh, r1 + outc, oacc[nf][2] * il1, oacc[nf][3] * il1);
    }
}

// ======== weight transposes: [K,N] -> [N,K] fp16, sigma16-permuted ==========
__device__ __forceinline__ int p16map(int k) {
    const int j = k & 15;
    return (k & ~15) | ((((j & 7) >> 1) * 4) + (j & 1) + (((j >> 3) & 1) * 2));
}

__global__ void transposeA_kernel(const float* __restrict__ wq, const float* __restrict__ wk,
                                  const float* __restrict__ wv, const float* __restrict__ wo,
                                  __half* __restrict__ wH) {
    __shared__ float t[32][33];
    const int z = blockIdx.z;
    const float* ip;
    size_t ob;
    if (z < 12) {
        const int l = z / 3, w = z % 3;
        ip = (w == 0 ? wq : (w == 1 ? wk : wv)) + (size_t)l * D * D;
        ob = OFF_QKV + (size_t)l * 3 * D * D + (size_t)w * D * D;
    } else {
        ip = wo + (size_t)(z - 12) * D * D;
        ob = OFF_OT + (size_t)(z - 12) * D * D;
    }
    const int n0 = blockIdx.x * 32, k0 = blockIdx.y * 32;
    const int tx = threadIdx.x, ty = threadIdx.y;
#pragma unroll
    for (int j = 0; j < 32; j += 8) t[ty + j][tx] = ip[(size_t)(k0 + ty + j) * D + n0 + tx];
    __syncthreads();
    const int kp = p16map(k0 + tx);
#pragma unroll
    for (int j = 0; j < 32; j += 8)
        wH[ob + (size_t)(n0 + ty + j) * D + kp] = __float2half_rn(t[tx][ty + j]);
}

__global__ void transposeB_kernel(const float* __restrict__ w1, const float* __restrict__ w2,
                                  __half* __restrict__ wH) {
    __shared__ float t[32][33];
    const int z = blockIdx.z;
    const float* ip;
    size_t ob;
    int Kd, Nd, n0, k0;
    if (z < 4) {
        ip = w1 + (size_t)z * D * F; ob = OFF_W1T + (size_t)z * D * F;
        Kd = D; Nd = F; n0 = blockIdx.x * 32; k0 = blockIdx.y * 32;
    } else {
        ip = w2 + (size_t)(z - 4) * F * D; ob = OFF_W2T + (size_t)(z - 4) * F * D;
        Kd = F; Nd = D; n0 = blockIdx.y * 32; k0 = blockIdx.x * 32;
    }
    const int tx = threadIdx.x, ty = threadIdx.y;
#pragma unroll
    for (int j = 0; j < 32; j += 8) t[ty + j][tx] = ip[(size_t)(k0 + ty + j) * Nd + n0 + tx];
    __syncthreads();
    const int kp = p16map(k0 + tx);
#pragma unroll
    for (int j = 0; j < 32; j += 8)
        wH[ob + (size_t)(n0 + ty + j) * Kd + kp] = __float2half_rn(t[tx][ty + j]);
}

// ---------------- event extraction ----------------
__global__ void build_events_kernel(const float* __restrict__ x,
                                    float* __restrict__ rows,
                                    float* __restrict__ maskb) {
    const int b = blockIdx.x;
    const int tid = threadIdx.x;
    __shared__ unsigned char sx[T];
    __shared__ int partial[256];

    for (int i = tid; i < E * 11; i += 256) rows[(size_t)b * E * 11 + i] = 0.f;
    for (int i = tid; i < E; i += 256) maskb[b * E + i] = 0.f;

    const float* xb = x + (size_t)b * T * C;
    for (int t = tid; t < T; t += 256) {
        unsigned v = 0;
#pragma unroll
        for (int c = 0; c < C; c++) v |= (xb[(size_t)t * C + c] > 0.5f) ? (1u << c) : 0u;
        sx[t] = (unsigned char)v;
    }
    __syncthreads();

    const int t0 = tid * 16;
    unsigned char prev = (t0 == 0) ? (unsigned char)(~sx[0]) : sx[t0 - 1];
    unsigned char smloc[16];
    int cnt = 0;
#pragma unroll
    for (int i = 0; i < 16; i++) {
        unsigned char cur = sx[t0 + i];
        smloc[i] = (unsigned char)(cur ^ prev);
        prev = cur;
        cnt += __popc((unsigned)smloc[i]);
    }
    partial[tid] = cnt;
    __syncthreads();
    if (tid == 0) {
        int run = 0;
        for (int i = 0; i < 256; i++) { int tmp = partial[i]; partial[i] = run; run += tmp; }
    }
    __syncthreads();

    int e = partial[tid];
    for (int i = 0; i < 16; i++) {
        const int t = t0 + i;
        unsigned m = smloc[i];
        while (m) {
            const int c = __ffs(m) - 1;
            m &= (m - 1);
            if (e < E) {
                const int v = (sx[t] >> c) & 1;
                int tt = t + 1;
                while (tt < T && (((sx[tt] >> c) & 1) == v)) tt++;
                float* r = rows + ((size_t)b * E + e) * 11;
                r[c] = 1.f;
                r[8] = (float)v;
                r[9] = (float)t / (float)(T - 1);
                r[10] = (float)(tt - t) / (float)T;
                maskb[b * E + e] = 1.f;
            }
            e++;
        }
    }
}

// ------- input projection (K=11): pw staged in smem, 8 rows per block -------
__global__ __launch_bounds__(256)
void proj_kernel(const float* __restrict__ rows,
                 const float* __restrict__ pw,
                 const float* __restrict__ pb,
                 float* __restrict__ h) {
    __shared__ float spw[11 * 512];
    __shared__ float sr[8][11];
    const int tid = threadIdx.x;
    for (int i = tid; i < 11 * 512; i += 256) spw[i] = pw[i];
    if (tid < 88)
        sr[tid / 11][tid % 11] = rows[(size_t)(blockIdx.x * 8 + tid / 11) * 11 + tid % 11];
    __syncthreads();

    const int w = tid >> 5, lane = tid & 31;
    const int row = blockIdx.x * 8 + w;
    float r[11];
#pragma unroll
    for (int j = 0; j < 11; j++) r[j] = sr[w][j];
#pragma unroll
    for (int i = 0; i < 4; i++) {
        const int col = i * 128 + lane * 4;
        float4 acc = *(const float4*)(pb + col);
#pragma unroll
        for (int j = 0; j < 11; j++) {
            const float4 wv = *(const float4*)(spw + j * 512 + col);
            acc.x += r[j] * wv.x; acc.y += r[j] * wv.y;
            acc.z += r[j] * wv.z; acc.w += r[j] * wv.w;
        }
        *(float4*)(h + (size_t)row * 512 + col) = acc;
    }
}

// ---- LayerNorm: warp per row -> fp16 sigma16 plane (mid-network only) ------
__global__ __launch_bounds__(256)
void ln_kernel(const float* __restrict__ h, const float* __restrict__ g,
               const float* __restrict__ bb, __half* __restrict__ zh) {
    const int row = blockIdx.x * 8 + (threadIdx.x >> 5);
    const int lane = threadIdx.x & 31;
    const float* hr = h + (size_t)row * D;

    float4 v[4];
    float s = 0.f, s2 = 0.f;
#pragma unroll
    for (int i = 0; i < 4; i++) {
        v[i] = *(const float4*)(hr + i * 128 + lane * 4);
        s += v[i].x + v[i].y + v[i].z + v[i].w;
        s2 += v[i].x * v[i].x + v[i].y * v[i].y + v[i].z * v[i].z + v[i].w * v[i].w;
    }
#pragma unroll
    for (int o = 16; o; o >>= 1) {
        s += __shfl_xor_sync(0xFFFFFFFFu, s, o);
        s2 += __shfl_xor_sync(0xFFFFFFFFu, s2, o);
    }
    const float mean = s * (1.f / D);
    const float var = s2 * (1.f / D) - mean * mean;
    const float inv = rsqrtf(var + 1e-5f);

#pragma unroll
    for (int i = 0; i < 4; i++) {
        const int cc = i * 128 + lane * 4;
        const float4 gg = *(const float4*)(g + cc);
        const float4 bv = *(const float4*)(bb + cc);
        float4 o;
        o.x = (v[i].x - mean) * inv * gg.x + bv.x;
        o.y = (v[i].y - mean) * inv * gg.y + bv.y;
        o.z = (v[i].z - mean) * inv * gg.z + bv.z;
        o.w = (v[i].w - mean) * inv * gg.w + bv.w;
        const int jj = cc & 12;
        const int pa = ((jj & 7) >> 1) * 4 + ((jj >> 3) & 1) * 2;
        const size_t base = (size_t)row * D + (cc & ~15);
        store_h2(zh, base + pa, o.x, o.y);
        store_h2(zh, base + pa + 4, o.z, o.w);
    }
}

// ---- fused final LN + masked pooling, stage 1: partials per 64-event chunk --
__global__ __launch_bounds__(256)
void lnpool1_kernel(const float* __restrict__ h, const float* __restrict__ g,
                    const float* __restrict__ bb, const float* __restrict__ maskb,
                    float* __restrict__ part, float* __restrict__ pcnt) {
    const int chunk = blockIdx.x, b = blockIdx.y;       // grid (16, B)
    const int tid = threadIdx.x;
    const int w = tid >> 5, lane = tid & 31;
    __shared__ float sg[D], sb2[D];
    __shared__ float wacc[8][D];
    __shared__ float wcnt[8];

    for (int i = tid; i < D; i += 256) { sg[i] = g[i]; sb2[i] = bb[i]; }
    __syncthreads();

    float acc[16];
#pragma unroll
    for (int i = 0; i < 16; i++) acc[i] = 0.f;
    float cw = 0.f;

    for (int r = 0; r < 8; r++) {
        const int e = chunk * 64 + w * 8 + r;
        const float mk = maskb[b * E + e];
        if (mk == 0.f) continue;
        cw += 1.f;
        const float* hr = h + ((size_t)(b * E) + e) * D;
        float4 v[4];
        float s = 0.f, s2 = 0.f;
#pragma unroll
        for (int i = 0; i < 4; i++) {
            v[i] = *(const float4*)(hr + i * 128 + lane * 4);
            s += v[i].x + v[i].y + v[i].z + v[i].w;
            s2 += v[i].x * v[i].x + v[i].y * v[i].y + v[i].z * v[i].z + v[i].w * v[i].w;
        }
#pragma unroll
        for (int o = 16; o; o >>= 1) {
            s += __shfl_xor_sync(0xFFFFFFFFu, s, o);
            s2 += __shfl_xor_sync(0xFFFFFFFFu, s2, o);
        }
        const float mean = s * (1.f / D);
        const float var = s2 * (1.f / D) - mean * mean;
        const float inv = rsqrtf(var + 1e-5f);
#pragma unroll
        for (int i = 0; i < 4; i++) {
            const int cc = i * 128 + lane * 4;
            acc[i * 4 + 0] += (v[i].x - mean) * inv * sg[cc + 0] + sb2[cc + 0];
            acc[i * 4 + 1] += (v[i].y - mean) * inv * sg[cc + 1] + sb2[cc + 1];
            acc[i * 4 + 2] += (v[i].z - mean) * inv * sg[cc + 2] + sb2[cc + 2];
            acc[i * 4 + 3] += (v[i].w - mean) * inv * sg[cc + 3] + sb2[cc + 3];
        }
    }
#pragma unroll
    for (int i = 0; i < 4; i++)
        *(float4*)(&wacc[w][i * 128 + lane * 4]) =
            make_float4(acc[i * 4], acc[i * 4 + 1], acc[i * 4 + 2], acc[i * 4 + 3]);
    if (lane == 0) wcnt[w] = cw;
    __syncthreads();

    for (int col = tid; col < D; col += 256) {
        float s = 0.f;
#pragma unroll
        for (int ww = 0; ww < 8; ww++) s += wacc[ww][col];
        part[(size_t)(b * 16 + chunk) * D + col] = s;
    }
    if (tid == 0) {
        float s = 0.f;
#pragma unroll
        for (int ww = 0; ww < 8; ww++) s += wcnt[ww];
        pcnt[b * 16 + chunk] = s;
    }
}

// ---- stage 2: reduce partials -> output ----
__global__ void lnpool2_kernel(const float* __restrict__ part,
                               const float* __restrict__ pcnt,
                               float* __restrict__ out) {
    const int b = blockIdx.x, d = threadIdx.x;     // grid B, 512 threads
    float s = 0.f;
#pragma unroll
    for (int c = 0; c < 16; c++) s += part[(size_t)(b * 16 + c) * D + d];
    float cnt = 0.f;
#pragma unroll
    for (int c = 0; c < 16; c++) cnt += pcnt[b * 16 + c];
    out[(size_t)b * D + d] = s / fmaxf(cnt, 1.f);
}

// ---------------- launch ----------------
extern "C" void kernel_launch(void* const* d_in, const int* in_sizes, int n_in,
                              void* d_out, int out_size) {
    const float* x      = (const float*)d_in[0];
    const float* proj_w = (const float*)d_in[1];
    const float* proj_b = (const float*)d_in[2];
    const float* wq     = (const float*)d_in[3];
    const float* wk     = (const float*)d_in[4];
    const float* wv     = (const float*)d_in[5];
    const float* wo     = (const float*)d_in[6];
    const float* ln1_g  = (const float*)d_in[7];
    const float* ln1_b  = (const float*)d_in[8];
    const float* w1     = (const float*)d_in[9];
    const float* b1     = (const float*)d_in[10];
    const float* w2     = (const float*)d_in[11];
    const float* b2     = (const float*)d_in[12];
    const float* ln2_g  = (const float*)d_in[13];
    const float* ln2_b  = (const float*)d_in[14];
    const float* lnf_g  = (const float*)d_in[15];
    const float* lnf_b  = (const float*)d_in[16];
    float* out = (float*)d_out;

    float *p_rows, *p_mask, *p_h, *p_pool, *p_pcnt;
    __half *p_qh, *p_kh, *p_vh, *p_zh, *p_oh, *p_fh, *p_wH;
    cudaGetSymbolAddress((void**)&p_rows, g_rows);
    cudaGetSymbolAddress((void**)&p_mask, g_mask);
    cudaGetSymbolAddress((void**)&p_h, g_h);
    cudaGetSymbolAddress((void**)&p_pool, g_pool);
    cudaGetSymbolAddress((void**)&p_pcnt, g_pcnt);
    cudaGetSymbolAddress((void**)&p_qh, g_qh);
    cudaGetSymbolAddress((void**)&p_kh, g_kh);
    cudaGetSymbolAddress((void**)&p_vh, g_vh);
    cudaGetSymbolAddress((void**)&p_zh, g_zh);
    cudaGetSymbolAddress((void**)&p_oh, g_oh);
    cudaGetSymbolAddress((void**)&p_fh, g_fh);
    cudaGetSymbolAddress((void**)&p_wH, g_wH);

    static bool attr_set = false;
    if (!attr_set) {
        cudaFuncSetAttribute(tgemm_kernel<0, 0, 0, 2>, cudaFuncAttributeMaxDynamicSharedMemorySize, GSMEM);
        cudaFuncSetAttribute(tgemm_kernel<0, 0, 1, 0>, cudaFuncAttributeMaxDynamicSharedMemorySize, GSMEM);
        cudaFuncSetAttribute(tgemm_kernel<1, 1, 0, 1>, cudaFuncAttributeMaxDynamicSharedMemorySize, GSMEM);
        cudaFuncSetAttribute(tgemm_kernel<1, 0, 1, 0>, cudaFuncAttributeMaxDynamicSharedMemorySize, GSMEM);
        cudaFuncSetAttribute(attn_mma_kernel, cudaFuncAttributeMaxDynamicSharedMemorySize, ASMEM);
        attr_set = true;
    }

    const int M = B * E;                       // 8192
    const dim3 gQKV(12, M / 128);
    const dim3 gD(D / 128, M / 128);
    const dim3 gF(F / 128, M / 128);
    const dim3 tb(32, 8);

    transposeA_kernel<<<dim3(16, 16, 16), tb>>>(wq, wk, wv, wo, p_wH);
    transposeB_kernel<<<dim3(64, 16, 8), tb>>>(w1, w2, p_wH);
    build_events_kernel<<<B, 256>>>(x, p_rows, p_mask);
    proj_kernel<<<M / 8, 256>>>(p_rows, proj_w, proj_b, p_h);

    for (int l = 0; l < NL; l++) {
        const size_t oQ = OFF_QKV + (size_t)l * 3 * D * D;
        const size_t oO = OFF_OT  + (size_t)l * D * D;
        const size_t o1 = OFF_W1T + (size_t)l * D * F;
        const size_t o2 = OFF_W2T + (size_t)l * D * F;

        ln_kernel<<<M / 8, 256>>>(p_h, ln1_g + l * D, ln1_b + l * D, p_zh);
        tgemm_kernel<0, 0, 0, 2><<<gQKV, 128, GSMEM>>>(
            p_zh, p_wH + oQ, nullptr, p_qh, p_kh, p_vh, M, 3 * D, D);
        attn_mma_kernel<<<dim3(E / 64, NH, B), 128, ASMEM>>>(
            p_qh, p_kh, p_vh, p_mask, p_oh);
        tgemm_kernel<0, 0, 1, 0><<<gD, 128, GSMEM>>>(
            p_oh, p_wH + oO, nullptr, p_h, nullptr, nullptr, M, D, D);

        ln_kernel<<<M / 8, 256>>>(p_h, ln2_g + l * D, ln2_b + l * D, p_zh);
        tgemm_kernel<1, 1, 0, 1><<<gF, 128, GSMEM>>>(
            p_zh, p_wH + o1, b1 + (size_t)l * F, p_fh, nullptr, nullptr, M, F, D);
        tgemm_kernel<1, 0, 1, 0><<<gD, 128, GSMEM>>>(
            p_fh, p_wH + o2, b2 + (size_t)l * D, p_h, nullptr, nullptr, M, D, F);
    }

    lnpool1_kernel<<<dim3(16, B), 256>>>(p_h, lnf_g, lnf_b, p_mask, p_pool, p_pcnt);
    lnpool2_kernel<<<B, D>>>(p_pool, p_pcnt, out);
}

// round 15
// speedup vs baseline: 1.0177x; 1.0177x over previous
#include <cuda_runtime.h>
#include <cuda_fp16.h>
#include <math.h>
#include <cstdint>

// Problem constants
constexpr int B = 8;
constexpr int T = 4096;
constexpr int C = 8;
constexpr int E = 1024;   // MAX_EVENTS
constexpr int D = 512;
constexpr int F = 2048;
constexpr int NL = 4;
constexpr int NH = 8;
constexpr int DH = 64;

// sigma16 k-permutation (within 16-groups): p16(j) = ((j&7)>>1)*4 + (j&1) + ((j>>3)&1)*2
// => fp16 m16n8k16 fragment k-set {2q,2q+1,2q+8,2q+9} is contiguous (one LDS.64).

// ---------------- device scratch (no allocation allowed) ----------------
__device__ float g_rows[B * E * 11];
__device__ float g_mask[B * E];
__device__ float g_h[(size_t)B * E * D];
__device__ float g_pool[B * 16 * D];              // LN+pool partials
__device__ float g_pcnt[B * 16];
// fp16 planes
__device__ __half g_qh[(size_t)B * E * D];        // sigma16 on dh
__device__ __half g_kh[(size_t)B * E * D];        // sigma16 on dh
__device__ __half g_vh[(size_t)B * E * D];        // plain
__device__ __half g_zh[(size_t)B * E * D];
__device__ __half g_oh[(size_t)B * E * D];
__device__ __half g_fh[(size_t)B * E * F];
__device__ __half g_wH[12582912];

constexpr size_t OFF_QKV = 0;                    // 4 * 3*D*D
constexpr size_t OFF_OT  = 3145728;              // 4 * D*D
constexpr size_t OFF_W1T = 4194304;              // 4 * D*F
constexpr size_t OFF_W2T = 8388608;              // 4 * F*D

// ================= PTX helpers =================
__device__ __forceinline__ uint32_t smem_u32(const void* p) {
    uint32_t a;
    asm("{ .reg .u64 t; cvta.to.shared.u64 t, %1; cvt.u32.u64 %0, t; }" : "=r"(a) : "l"(p));
    return a;
}
__device__ __forceinline__ void cpasync16(uint32_t dst, const void* src) {
    asm volatile("cp.async.cg.shared.global [%0], [%1], 16;" :: "r"(dst), "l"(src));
}
#define CP_COMMIT() asm volatile("cp.async.commit_group;" ::: "memory")
#define CP_WAIT(n)  asm volatile("cp.async.wait_group %0;" :: "n"(n) : "memory")

__device__ __forceinline__ void mma_fp16(float* c,
                                         uint32_t a0, uint32_t a1, uint32_t a2, uint32_t a3,
                                         uint32_t b0, uint32_t b1) {
    asm volatile(
        "mma.sync.aligned.m16n8k16.row.col.f32.f16.f16.f32 "
        "{%0,%1,%2,%3}, {%4,%5,%6,%7}, {%8,%9}, {%0,%1,%2,%3};"
        : "+f"(c[0]), "+f"(c[1]), "+f"(c[2]), "+f"(c[3])
        : "r"(a0), "r"(a1), "r"(a2), "r"(a3), "r"(b0), "r"(b1));
}
__device__ __forceinline__ void ldm4t(uint32_t& r0, uint32_t& r1, uint32_t& r2, uint32_t& r3,
                                      uint32_t addr) {
    asm volatile("ldmatrix.sync.aligned.m8n8.x4.trans.shared.b16 {%0,%1,%2,%3}, [%4];"
                 : "=r"(r0), "=r"(r1), "=r"(r2), "=r"(r3) : "r"(addr));
}

__device__ __forceinline__ void store_h2(__half* P, size_t idx, float x, float y) {
    __half2 h;
    h.x = __float2half_rn(x);
    h.y = __float2half_rn(y);
    *(__half2*)(P + idx) = h;
}

// ---------------- GELU (tanh approximation, matches jax.nn.gelu default) ----
__device__ __forceinline__ float gelu_f(float v) {
    const float c = 0.7978845608028654f;
    float t = tanhf(c * (v + 0.044715f * v * v * v));
    return 0.5f * v * (1.f + t);
}

// ================= fp16 mma.sync GEMM ========================================
// C[M,N] = A[M,K] @ W[K,N]; A and W fp16, K-major for W ([N,K]), sigma16-
// permuted on k. Block tile 128x128, BK=32, 128 threads (4 warps, 2x2 of
// 64x64 warp tiles). Double-buffered cp.async, ONE __syncthreads per K-iter.
// (R13 configuration — BK=64 tested in R14 and regressed; reverted.)
// OUT: 0 = fp32 C0 (opt residual), 1 = fp16 sigma16 plane,
//      2 = SPLIT3 QKV (q,k fp16 sigma16 planes; v fp16 plain plane).
constexpr int PLANE_B = 128 * 96;            // 12288 bytes per plane tile
constexpr int BUF_B = 2 * PLANE_B;           // 24576 bytes per buffer
constexpr int GSMEM = 2 * BUF_B;             // 49152 bytes (2 buffers)

template <int BIAS, int GELU_, int RES, int OUT>
__global__ __launch_bounds__(128)
void tgemm_kernel(const __half* __restrict__ Ah, const __half* __restrict__ Wh,
                  const float* __restrict__ bias,
                  void* __restrict__ C0v, void* __restrict__ C1v, void* __restrict__ C2v,
                  int M, int N, int K) {
    extern __shared__ char smem[];
    const uint32_t sb = smem_u32(smem);
    const int tid = threadIdx.x;
    const int wid = tid >> 5, lane = tid & 31;
    const int g = lane >> 2, q = lane & 3;
    const int wm = (wid & 1) * 64;
    const int wn = (wid >> 1) * 64;
    const int bn = blockIdx.x;
    const int n0 = bn * 128;
    const int m0 = blockIdx.y * 128;

    float acc[4][8][4];
#pragma unroll
    for (int i = 0; i < 4; i++)
#pragma unroll
        for (int j = 0; j < 8; j++)
#pragma unroll
            for (int k = 0; k < 4; k++) acc[i][j][k] = 0.f;

    auto load_tile = [&](int bf, int i) {
        const int k0 = i * 32;
        const __half* gA = Ah + (size_t)m0 * K + k0;
        const __half* gW = Wh + (size_t)n0 * K + k0;
        const uint32_t base = sb + (uint32_t)bf * BUF_B;
#pragma unroll
        for (int j = 0; j < 4; j++) {
            const int ch = j * 128 + tid;          // 0..511
            const int row = ch >> 2, c16 = ch & 3;
            const uint32_t so = (uint32_t)(row * 96 + c16 * 16);
            cpasync16(base + so, gA + (size_t)row * K + c16 * 8);
            cpasync16(base + PLANE_B + so, gW + (size_t)row * K + c16 * 8);
        }
        CP_COMMIT();
    };

    const int NK = K >> 5;
    load_tile(0, 0);
    for (int i = 0; i < NK; i++) {
        CP_WAIT(0);                           // only load(i) pending
        __syncthreads();                      // tile i visible; buf (i+1)&1 free
        if (i + 1 < NK) load_tile((i + 1) & 1, i + 1);

        const __half* sA = reinterpret_cast<const __half*>(smem) + (i & 1) * (BUF_B / 2);
        const __half* sB = sA + PLANE_B / 2;

#pragma unroll
        for (int s = 0; s < 2; s++) {                  // two k16 steps per BK=32
            const int fo = s * 16 + q * 4;
            uint32_t af[4][4];
#pragma unroll
            for (int mt = 0; mt < 4; mt++) {
                const int r0 = wm + mt * 16 + g;
                const uint2 x0 = *(const uint2*)(sA + r0 * 48 + fo);
                const uint2 x1 = *(const uint2*)(sA + (r0 + 8) * 48 + fo);
                af[mt][0] = x0.x; af[mt][2] = x0.y;
                af[mt][1] = x1.x; af[mt][3] = x1.y;
            }
#pragma unroll
            for (int nt = 0; nt < 8; nt++) {
                const int cc = wn + nt * 8 + g;
                const uint2 bv = *(const uint2*)(sB + cc * 48 + fo);
#pragma unroll
                for (int mt = 0; mt < 4; mt++)
                    mma_fp16(acc[mt][nt], af[mt][0], af[mt][1], af[mt][2], af[mt][3],
                             bv.x, bv.y);
            }
        }
    }

    // ---------------- epilogue ----------------
    if (OUT == 2) {
        const int seg = bn >> 2;
        const int c0 = (bn & 3) * 128;
#pragma unroll
        for (int mt = 0; mt < 4; mt++) {
            const int r0 = m0 + wm + mt * 16 + g;
#pragma unroll
            for (int nt = 0; nt < 8; nt++) {
                const int cbase = c0 + wn + nt * 8;
                const float2 v0 = make_float2(acc[mt][nt][0], acc[mt][nt][1]);
                const float2 v1 = make_float2(acc[mt][nt][2], acc[mt][nt][3]);
                if (seg < 2) {   // q,k: fp16 sigma16 plane
                    __half* Ch = (seg == 0) ? (__half*)C0v : (__half*)C1v;
                    const int outc = (cbase & ~15) + q * 4 + ((cbase >> 3) & 1) * 2;
                    store_h2(Ch, (size_t)r0 * 512 + outc, v0.x, v0.y);
                    store_h2(Ch, (size_t)(r0 + 8) * 512 + outc, v1.x, v1.y);
                } else {         // v: fp16 plain plane
                    __half* Vh = (__half*)C2v;
                    const size_t i0 = (size_t)r0 * 512 + cbase + 2 * q;
                    store_h2(Vh, i0, v0.x, v0.y);
                    store_h2(Vh, i0 + (size_t)8 * 512, v1.x, v1.y);
                }
            }
        }
    } else {
#pragma unroll
        for (int mt = 0; mt < 4; mt++) {
            const int r0 = m0 + wm + mt * 16 + g;
#pragma unroll
            for (int nt = 0; nt < 8; nt++) {
                const int cbase = n0 + wn + nt * 8;
                float2 v0 = make_float2(acc[mt][nt][0], acc[mt][nt][1]);
                float2 v1 = make_float2(acc[mt][nt][2], acc[mt][nt][3]);
                if (BIAS) {
                    const float2 bb = *(const float2*)(bias + cbase + 2 * q);
                    v0.x += bb.x; v0.y += bb.y; v1.x += bb.x; v1.y += bb.y;
                }
                if (GELU_) {
                    v0.x = gelu_f(v0.x); v0.y = gelu_f(v0.y);
                    v1.x = gelu_f(v1.x); v1.y = gelu_f(v1.y);
                }
                if (OUT == 0) {
                    float* p0 = (float*)C0v + (size_t)r0 * N + cbase + 2 * q;
                    float* p1 = (float*)C0v + (size_t)(r0 + 8) * N + cbase + 2 * q;
                    if (RES) {
                        const float2 o0 = *(const float2*)p0;
                        const float2 o1 = *(const float2*)p1;
                        v0.x += o0.x; v0.y += o0.y; v1.x += o1.x; v1.y += o1.y;
                    }
                    *(float2*)p0 = v0;
                    *(float2*)p1 = v1;
                } else {   // OUT == 1: fp16 sigma16 plane
                    const int outc = (cbase & ~15) + q * 4 + ((cbase >> 3) & 1) * 2;
                    __half* Ch = (__half*)C0v;
                    store_h2(Ch, (size_t)r0 * N + outc, v0.x, v0.y);
                    store_h2(Ch, (size_t)(r0 + 8) * N + outc, v1.x, v1.y);
                }
            }
        }
    }
}

// ================= fp16 mma flash attention ==================================
// grid (E/64, NH, B), 128 threads (4 warps x 16 q-rows). 64-key K/V tiles,
// double-buffered cp.async, single __syncthreads per iter.
// QK: fp16. PV: single fp16 mma, V B-frags via ldmatrix.trans.
constexpr int AOFF_K  = 5120;     // Q at 0 (64 x 80); K 2 x 5120
constexpr int AOFF_VH = 15360;    // 2 x 4608 (64 x 72, 144B stride)
constexpr int AOFF_P  = 24576;    // 64 x 80 (sigma16 on key dim)
constexpr int AOFF_MB = (24576 + 5120) * 2;   // byte offset masks (2 x 256B)
constexpr int ASMEM = AOFF_MB + 512;          // 59904 bytes

__global__ __launch_bounds__(128)
void attn_mma_kernel(const __half* __restrict__ Qg, const __half* __restrict__ Kg,
                     const __half* __restrict__ Vg,
                     const float* __restrict__ maskb, __half* __restrict__ Oh) {
    extern __shared__ char smraw[];
    __half* sh = (__half*)smraw;
    const uint32_t sb = smem_u32(smraw);
    const int qb = blockIdx.x, hd = blockIdx.y, b = blockIdx.z;
    const int tid = threadIdx.x, wid = tid >> 5, lane = tid & 31;
    const int g = lane >> 2, q = lane & 3;
    const int wr = wid * 16;
    const int koff = ((lane >> 3) & 1) * 8 + (lane & 7);
    const int dhoff = (lane >> 4) * 8;

    auto load_kv = [&](int buf, int i) {
        const size_t gbase = ((size_t)(b * E) + i * 64) * D + hd * DH;
        const __half* Kp = Kg + gbase;
        const __half* Vp = Vg + gbase;
        const uint32_t sK = sb + (uint32_t)(AOFF_K + buf * 5120) * 2;
        const uint32_t sV = sb + (uint32_t)(AOFF_VH + buf * 4608) * 2;
#pragma unroll
        for (int j = 0; j < 4; j++) {
            const int ch = j * 128 + tid;          // 512 chunks: 64 rows x 8
            const int r = ch >> 3, c = ch & 7;
            cpasync16(sK + r * 160 + c * 16, Kp + (size_t)r * D + c * 8);
            cpasync16(sV + r * 144 + c * 16, Vp + (size_t)r * D + c * 8);
        }
        if (tid < 16)
            cpasync16(sb + AOFF_MB + buf * 256 + tid * 16,
                      maskb + b * E + i * 64 + tid * 4);
        CP_COMMIT();
    };
    load_kv(0, 0);

    // Q tile -> smem (sigma16 on dh already applied by QKV GEMM)
    const __half* Qp = Qg + ((size_t)(b * E) + qb * 64) * D + hd * DH;
#pragma unroll
    for (int j = 0; j < 4; j++) {
        const int ch = j * 128 + tid;
        const int r = ch >> 3, c = ch & 7;
        *(uint4*)(sh + r * 80 + c * 8) = *(const uint4*)(Qp + (size_t)r * D + c * 8);
    }
    __syncthreads();

    uint32_t qa[4][4];
#pragma unroll
    for (int kg = 0; kg < 4; kg++) {
        const uint2 x0 = *(const uint2*)(sh + (wr + g) * 80 + kg * 16 + q * 4);
        const uint2 x1 = *(const uint2*)(sh + (wr + g + 8) * 80 + kg * 16 + q * 4);
        qa[kg][0] = x0.x; qa[kg][2] = x0.y;
        qa[kg][1] = x1.x; qa[kg][3] = x1.y;
    }
    __syncwarp();

    float m0 = -1e30f, m1 = -1e30f, l0 = 0.f, l1 = 0.f;
    float oacc[8][4];
#pragma unroll
    for (int nf = 0; nf < 8; nf++)
#pragma unroll
        for (int k = 0; k < 4; k++) oacc[nf][k] = 0.f;

    __half* Ph0 = sh + AOFF_P + (wr + g) * 80;
    __half* Ph1 = sh + AOFF_P + (wr + g + 8) * 80;

    for (int i = 0; i < 16; i++) {
        const int buf = i & 1;
        CP_WAIT(0);                       // only load(i) pending
        __syncthreads();                  // tile i visible; buf (i+1)&1 free
        if (i + 1 < 16) load_kv((i + 1) & 1, i + 1);

        const __half* sK = sh + AOFF_K + buf * 5120;
        const uint32_t sV32 = sb + (uint32_t)(AOFF_VH + buf * 4608) * 2;
        const float* kmb = (const float*)(smraw + AOFF_MB + buf * 256);

        // ---- scores: S = Q K^T (fp16) ----
        float sc[8][4];
#pragma unroll
        for (int nf = 0; nf < 8; nf++)
#pragma unroll
            for (int k = 0; k < 4; k++) sc[nf][k] = 0.f;
#pragma unroll
        for (int kg = 0; kg < 4; kg++) {
#pragma unroll
            for (int nf = 0; nf < 8; nf++) {
                const uint2 bv = *(const uint2*)(sK + (nf * 8 + g) * 80 + kg * 16 + q * 4);
                mma_fp16(sc[nf], qa[kg][0], qa[kg][1], qa[kg][2], qa[kg][3], bv.x, bv.y);
            }
        }

        // ---- scale (1/8) + mask + online softmax ----
        float mt0 = -1e30f, mt1 = -1e30f;
#pragma unroll
        for (int nf = 0; nf < 8; nf++) {
            sc[nf][0] *= 0.125f; sc[nf][1] *= 0.125f;
            sc[nf][2] *= 0.125f; sc[nf][3] *= 0.125f;
            const float mk0 = kmb[nf * 8 + 2 * q];
            const float mk1 = kmb[nf * 8 + 2 * q + 1];
            if (mk0 == 0.f) { sc[nf][0] = -1e9f; sc[nf][2] = -1e9f; }
            if (mk1 == 0.f) { sc[nf][1] = -1e9f; sc[nf][3] = -1e9f; }
            mt0 = fmaxf(mt0, fmaxf(sc[nf][0], sc[nf][1]));
            mt1 = fmaxf(mt1, fmaxf(sc[nf][2], sc[nf][3]));
        }
        mt0 = fmaxf(mt0, __shfl_xor_sync(0xFFFFFFFFu, mt0, 1));
        mt0 = fmaxf(mt0, __shfl_xor_sync(0xFFFFFFFFu, mt0, 2));
        mt1 = fmaxf(mt1, __shfl_xor_sync(0xFFFFFFFFu, mt1, 1));
        mt1 = fmaxf(mt1, __shfl_xor_sync(0xFFFFFFFFu, mt1, 2));
        const float mn0 = fmaxf(m0, mt0), mn1 = fmaxf(m1, mt1);
        const float al0 = __expf(m0 - mn0), al1 = __expf(m1 - mn1);
        m0 = mn0; m1 = mn1;

        float ps0 = 0.f, ps1 = 0.f;
#pragma unroll
        for (int nf = 0; nf < 8; nf++) {
            const float p0 = __expf(sc[nf][0] - mn0);
            const float p1 = __expf(sc[nf][1] - mn0);
            const float p2 = __expf(sc[nf][2] - mn1);
            const float p3 = __expf(sc[nf][3] - mn1);
            ps0 += p0 + p1; ps1 += p2 + p3;
            const int pp = (nf >> 1) * 16 + q * 4 + (nf & 1) * 2;   // sigma16 pos
            store_h2(Ph0, pp, p0, p1);
            store_h2(Ph1, pp, p2, p3);
            oacc[nf][0] *= al0; oacc[nf][1] *= al0;
            oacc[nf][2] *= al1; oacc[nf][3] *= al1;
        }
        ps0 += __shfl_xor_sync(0xFFFFFFFFu, ps0, 1);
        ps0 += __shfl_xor_sync(0xFFFFFFFFu, ps0, 2);
        ps1 += __shfl_xor_sync(0xFFFFFFFFu, ps1, 1);
        ps1 += __shfl_xor_sync(0xFFFFFFFFu, ps1, 2);
        l0 = l0 * al0 + ps0; l1 = l1 * al1 + ps1;
        __syncwarp();   // P visible within warp (A-frags read only own warp rows)

        // ---- O += P V (single fp16 mma per fragment) ----
#pragma unroll
        for (int kg = 0; kg < 4; kg++) {
            const int po = kg * 16 + q * 4;
            const uint2 x0 = *(const uint2*)(Ph0 + po);
            const uint2 x1 = *(const uint2*)(Ph1 + po);
            const uint32_t rowb = (uint32_t)((kg * 16 + koff) * 144 + dhoff * 2);
#pragma unroll
            for (int nfp = 0; nfp < 4; nfp++) {
                uint32_t b0, b1, b2, b3;
                ldm4t(b0, b1, b2, b3, sV32 + rowb + nfp * 32);
                mma_fp16(oacc[2 * nfp],     x0.x, x1.x, x0.y, x1.y, b0, b1);
                mma_fp16(oacc[2 * nfp + 1], x0.x, x1.x, x0.y, x1.y, b2, b3);
            }
        }
    }

    // O -> fp16 sigma16-permuted plane (feeds WO GEMM)
    const float il0 = 1.f / l0, il1 = 1.f / l1;
    const size_t r0 = ((size_t)(b * E) + qb * 64 + wr + g) * D + hd * DH;
    const size_t r1 = r0 + (size_t)8 * D;
#pragma unroll
    for (int nf = 0; nf < 8; nf++) {
        const int outc = (nf >> 1) * 16 + q * 4 + (nf & 1) * 2;
        store_h2(Oh, r0 + outc, oacc[nf][0] * il0, oacc[nf][1] * il0);
        store_h2(Oh, r1 + outc, oacc[nf][2] * il1, oacc[nf][3] * il1);
    }
}

// ======== weight transposes: [K,N] -> [N,K] fp16, sigma16-permuted ==========
__device__ __forceinline__ int p16map(int k) {
    const int j = k & 15;
    return (k & ~15) | ((((j & 7) >> 1) * 4) + (j & 1) + (((j >> 3) & 1) * 2));
}

__global__ void transposeA_kernel(const float* __restrict__ wq, const float* __restrict__ wk,
                                  const float* __restrict__ wv, const float* __restrict__ wo,
                                  __half* __restrict__ wH) {
    __shared__ float t[32][33];
    const int z = blockIdx.z;
    const float* ip;
    size_t ob;
    if (z < 12) {
        const int l = z / 3, w = z % 3;
        ip = (w == 0 ? wq : (w == 1 ? wk : wv)) + (size_t)l * D * D;
        ob = OFF_QKV + (size_t)l * 3 * D * D + (size_t)w * D * D;
    } else {
        ip = wo + (size_t)(z - 12) * D * D;
        ob = OFF_OT + (size_t)(z - 12) * D * D;
    }
    const int n0 = blockIdx.x * 32, k0 = blockIdx.y * 32;
    const int tx = threadIdx.x, ty = threadIdx.y;
#pragma unroll
    for (int j = 0; j < 32; j += 8) t[ty + j][tx] = ip[(size_t)(k0 + ty + j) * D + n0 + tx];
    __syncthreads();
    const int kp = p16map(k0 + tx);
#pragma unroll
    for (int j = 0; j < 32; j += 8)
        wH[ob + (size_t)(n0 + ty + j) * D + kp] = __float2half_rn(t[tx][ty + j]);
}

__global__ void transposeB_kernel(const float* __restrict__ w1, const float* __restrict__ w2,
                                  __half* __restrict__ wH) {
    __shared__ float t[32][33];
    const int z = blockIdx.z;
    const float* ip;
    size_t ob;
    int Kd, Nd, n0, k0;
    if (z < 4) {
        ip = w1 + (size_t)z * D * F; ob = OFF_W1T + (size_t)z * D * F;
        Kd = D; Nd = F; n0 = blockIdx.x * 32; k0 = blockIdx.y * 32;
    } else {
        ip = w2 + (size_t)(z - 4) * F * D; ob = OFF_W2T + (size_t)(z - 4) * F * D;
        Kd = F; Nd = D; n0 = blockIdx.y * 32; k0 = blockIdx.x * 32;
    }
    const int tx = threadIdx.x, ty = threadIdx.y;
#pragma unroll
    for (int j = 0; j < 32; j += 8) t[ty + j][tx] = ip[(size_t)(k0 + ty + j) * Nd + n0 + tx];
    __syncthreads();
    const int kp = p16map(k0 + tx);
#pragma unroll
    for (int j = 0; j < 32; j += 8)
        wH[ob + (size_t)(n0 + ty + j) * Kd + kp] = __float2half_rn(t[tx][ty + j]);
}

// ---------------- event extraction ----------------
__global__ void build_events_kernel(const float* __restrict__ x,
                                    float* __restrict__ rows,
                                    float* __restrict__ maskb) {
    const int b = blockIdx.x;
    const int tid = threadIdx.x;
    __shared__ unsigned char sx[T];
    __shared__ int partial[256];

    for (int i = tid; i < E * 11; i += 256) rows[(size_t)b * E * 11 + i] = 0.f;
    for (int i = tid; i < E; i += 256) maskb[b * E + i] = 0.f;

    const float* xb = x + (size_t)b * T * C;
    for (int t = tid; t < T; t += 256) {
        unsigned v = 0;
#pragma unroll
        for (int c = 0; c < C; c++) v |= (xb[(size_t)t * C + c] > 0.5f) ? (1u << c) : 0u;
        sx[t] = (unsigned char)v;
    }
    __syncthreads();

    const int t0 = tid * 16;
    unsigned char prev = (t0 == 0) ? (unsigned char)(~sx[0]) : sx[t0 - 1];
    unsigned char smloc[16];
    int cnt = 0;
#pragma unroll
    for (int i = 0; i < 16; i++) {
        unsigned char cur = sx[t0 + i];
        smloc[i] = (unsigned char)(cur ^ prev);
        prev = cur;
        cnt += __popc((unsigned)smloc[i]);
    }
    partial[tid] = cnt;
    __syncthreads();
    if (tid == 0) {
        int run = 0;
        for (int i = 0; i < 256; i++) { int tmp = partial[i]; partial[i] = run; run += tmp; }
    }
    __syncthreads();

    int e = partial[tid];
    for (int i = 0; i < 16; i++) {
        const int t = t0 + i;
        unsigned m = smloc[i];
        while (m) {
            const int c = __ffs(m) - 1;
            m &= (m - 1);
            if (e < E) {
                const int v = (sx[t] >> c) & 1;
                int tt = t + 1;
                while (tt < T && (((sx[tt] >> c) & 1) == v)) tt++;
                float* r = rows + ((size_t)b * E + e) * 11;
                r[c] = 1.f;
                r[8] = (float)v;
                r[9] = (float)t / (float)(T - 1);
                r[10] = (float)(tt - t) / (float)T;
                maskb[b * E + e] = 1.f;
            }
            e++;
        }
    }
}

// ----- input projection (K=11): pw staged in smem, 32 rows per block --------
__global__ __launch_bounds__(256)
void proj_kernel(const float* __restrict__ rows,
                 const float* __restrict__ pw,
                 const float* __restrict__ pb,
                 float* __restrict__ h) {
    __shared__ float spw[11 * 512];
    __shared__ float sr[32][11];
    const int tid = threadIdx.x;
    for (int i = tid; i < 11 * 512; i += 256) spw[i] = pw[i];
    for (int i = tid; i < 352; i += 256)
        sr[i / 11][i % 11] = rows[(size_t)(blockIdx.x * 32 + i / 11) * 11 + i % 11];
    __syncthreads();

    const int w = tid >> 5, lane = tid & 31;
#pragma unroll
    for (int r = 0; r < 4; r++) {
        const int lr = w * 4 + r;                       // local row 0..31
        const int row = blockIdx.x * 32 + lr;
        float rr[11];
#pragma unroll
        for (int j = 0; j < 11; j++) rr[j] = sr[lr][j];
#pragma unroll
        for (int i = 0; i < 4; i++) {
            const int col = i * 128 + lane * 4;
            float4 acc = *(const float4*)(pb + col);
#pragma unroll
            for (int j = 0; j < 11; j++) {
                const float4 wv = *(const float4*)(spw + j * 512 + col);
                acc.x += rr[j] * wv.x; acc.y += rr[j] * wv.y;
                acc.z += rr[j] * wv.z; acc.w += rr[j] * wv.w;
            }
            *(float4*)(h + (size_t)row * 512 + col) = acc;
        }
    }
}

// ---- LayerNorm: warp per row -> fp16 sigma16 plane (mid-network only) ------
__global__ __launch_bounds__(256)
void ln_kernel(const float* __restrict__ h, const float* __restrict__ g,
               const float* __restrict__ bb, __half* __restrict__ zh) {
    const int row = blockIdx.x * 8 + (threadIdx.x >> 5);
    const int lane = threadIdx.x & 31;
    const float* hr = h + (size_t)row * D;

    float4 v[4];
    float s = 0.f, s2 = 0.f;
#pragma unroll
    for (int i = 0; i < 4; i++) {
        v[i] = *(const float4*)(hr + i * 128 + lane * 4);
        s += v[i].x + v[i].y + v[i].z + v[i].w;
        s2 += v[i].x * v[i].x + v[i].y * v[i].y + v[i].z * v[i].z + v[i].w * v[i].w;
    }
#pragma unroll
    for (int o = 16; o; o >>= 1) {
        s += __shfl_xor_sync(0xFFFFFFFFu, s, o);
        s2 += __shfl_xor_sync(0xFFFFFFFFu, s2, o);
    }
    const float mean = s * (1.f / D);
    const float var = s2 * (1.f / D) - mean * mean;
    const float inv = rsqrtf(var + 1e-5f);

#pragma unroll
    for (int i = 0; i < 4; i++) {
        const int cc = i * 128 + lane * 4;
        const float4 gg = *(const float4*)(g + cc);
        const float4 bv = *(const float4*)(bb + cc);
        float4 o;
        o.x = (v[i].x - mean) * inv * gg.x + bv.x;
        o.y = (v[i].y - mean) * inv * gg.y + bv.y;
        o.z = (v[i].z - mean) * inv * gg.z + bv.z;
        o.w = (v[i].w - mean) * inv * gg.w + bv.w;
        const int jj = cc & 12;
        const int pa = ((jj & 7) >> 1) * 4 + ((jj >> 3) & 1) * 2;
        const size_t base = (size_t)row * D + (cc & ~15);
        store_h2(zh, base + pa, o.x, o.y);
        store_h2(zh, base + pa + 4, o.z, o.w);
    }
}

// ---- fused final LN + masked pooling, stage 1: partials per 64-event chunk --
__global__ __launch_bounds__(256)
void lnpool1_kernel(const float* __restrict__ h, const float* __restrict__ g,
                    const float* __restrict__ bb, const float* __restrict__ maskb,
                    float* __restrict__ part, float* __restrict__ pcnt) {
    const int chunk = blockIdx.x, b = blockIdx.y;       // grid (16, B)
    const int tid = threadIdx.x;
    const int w = tid >> 5, lane = tid & 31;
    __shared__ float sg[D], sb2[D];
    __shared__ float wacc[8][D];
    __shared__ float wcnt[8];

    for (int i = tid; i < D; i += 256) { sg[i] = g[i]; sb2[i] = bb[i]; }
    __syncthreads();

    float acc[16];
#pragma unroll
    for (int i = 0; i < 16; i++) acc[i] = 0.f;
    float cw = 0.f;

    for (int r = 0; r < 8; r++) {
        const int e = chunk * 64 + w * 8 + r;
        const float mk = maskb[b * E + e];
        if (mk == 0.f) continue;
        cw += 1.f;
        const float* hr = h + ((size_t)(b * E) + e) * D;
        float4 v[4];
        float s = 0.f, s2 = 0.f;
#pragma unroll
        for (int i = 0; i < 4; i++) {
            v[i] = *(const float4*)(hr + i * 128 + lane * 4);
            s += v[i].x + v[i].y + v[i].z + v[i].w;
            s2 += v[i].x * v[i].x + v[i].y * v[i].y + v[i].z * v[i].z + v[i].w * v[i].w;
        }
#pragma unroll
        for (int o = 16; o; o >>= 1) {
            s += __shfl_xor_sync(0xFFFFFFFFu, s, o);
            s2 += __shfl_xor_sync(0xFFFFFFFFu, s2, o);
        }
        const float mean = s * (1.f / D);
        const float var = s2 * (1.f / D) - mean * mean;
        const float inv = rsqrtf(var + 1e-5f);
#pragma unroll
        for (int i = 0; i < 4; i++) {
            const int cc = i * 128 + lane * 4;
            acc[i * 4 + 0] += (v[i].x - mean) * inv * sg[cc + 0] + sb2[cc + 0];
            acc[i * 4 + 1] += (v[i].y - mean) * inv * sg[cc + 1] + sb2[cc + 1];
            acc[i * 4 + 2] += (v[i].z - mean) * inv * sg[cc + 2] + sb2[cc + 2];
            acc[i * 4 + 3] += (v[i].w - mean) * inv * sg[cc + 3] + sb2[cc + 3];
        }
    }
#pragma unroll
    for (int i = 0; i < 4; i++)
        *(float4*)(&wacc[w][i * 128 + lane * 4]) =
            make_float4(acc[i * 4], acc[i * 4 + 1], acc[i * 4 + 2], acc[i * 4 + 3]);
    if (lane == 0) wcnt[w] = cw;
    __syncthreads();

    for (int col = tid; col < D; col += 256) {
        float s = 0.f;
#pragma unroll
        for (int ww = 0; ww < 8; ww++) s += wacc[ww][col];
        part[(size_t)(b * 16 + chunk) * D + col] = s;
    }
    if (tid == 0) {
        float s = 0.f;
#pragma unroll
        for (int ww = 0; ww < 8; ww++) s += wcnt[ww];
        pcnt[b * 16 + chunk] = s;
    }
}

// ---- stage 2: reduce partials -> output ----
__global__ void lnpool2_kernel(const float* __restrict__ part,
                               const float* __restrict__ pcnt,
                               float* __restrict__ out) {
    const int b = blockIdx.x, d = threadIdx.x;     // grid B, 512 threads
    float s = 0.f;
#pragma unroll
    for (int c = 0; c < 16; c++) s += part[(size_t)(b * 16 + c) * D + d];
    float cnt = 0.f;
#pragma unroll
    for (int c = 0; c < 16; c++) cnt += pcnt[b * 16 + c];
    out[(size_t)b * D + d] = s / fmaxf(cnt, 1.f);
}

// ---------------- launch ----------------
extern "C" void kernel_launch(void* const* d_in, const int* in_sizes, int n_in,
                              void* d_out, int out_size) {
    const float* x      = (const float*)d_in[0];
    const float* proj_w = (const float*)d_in[1];
    const float* proj_b = (const float*)d_in[2];
    const float* wq     = (const float*)d_in[3];
    const float* wk     = (const float*)d_in[4];
    const float* wv     = (const float*)d_in[5];
    const float* wo     = (const float*)d_in[6];
    const float* ln1_g  = (const float*)d_in[7];
    const float* ln1_b  = (const float*)d_in[8];
    const float* w1     = (const float*)d_in[9];
    const float* b1     = (const float*)d_in[10];
    const float* w2     = (const float*)d_in[11];
    const float* b2     = (const float*)d_in[12];
    const float* ln2_g  = (const float*)d_in[13];
    const float* ln2_b  = (const float*)d_in[14];
    const float* lnf_g  = (const float*)d_in[15];
    const float* lnf_b  = (const float*)d_in[16];
    float* out = (float*)d_out;

    float *p_rows, *p_mask, *p_h, *p_pool, *p_pcnt;
    __half *p_qh, *p_kh, *p_vh, *p_zh, *p_oh, *p_fh, *p_wH;
    cudaGetSymbolAddress((void**)&p_rows, g_rows);
    cudaGetSymbolAddress((void**)&p_mask, g_mask);
    cudaGetSymbolAddress((void**)&p_h, g_h);
    cudaGetSymbolAddress((void**)&p_pool, g_pool);
    cudaGetSymbolAddress((void**)&p_pcnt, g_pcnt);
    cudaGetSymbolAddress((void**)&p_qh, g_qh);
    cudaGetSymbolAddress((void**)&p_kh, g_kh);
    cudaGetSymbolAddress((void**)&p_vh, g_vh);
    cudaGetSymbolAddress((void**)&p_zh, g_zh);
    cudaGetSymbolAddress((void**)&p_oh, g_oh);
    cudaGetSymbolAddress((void**)&p_fh, g_fh);
    cudaGetSymbolAddress((void**)&p_wH, g_wH);

    static bool attr_set = false;
    if (!attr_set) {
        cudaFuncSetAttribute(tgemm_kernel<0, 0, 0, 2>, cudaFuncAttributeMaxDynamicSharedMemorySize, GSMEM);
        cudaFuncSetAttribute(tgemm_kernel<0, 0, 1, 0>, cudaFuncAttributeMaxDynamicSharedMemorySize, GSMEM);
        cudaFuncSetAttribute(tgemm_kernel<1, 1, 0, 1>, cudaFuncAttributeMaxDynamicSharedMemorySize, GSMEM);
        cudaFuncSetAttribute(tgemm_kernel<1, 0, 1, 0>, cudaFuncAttributeMaxDynamicSharedMemorySize, GSMEM);
        cudaFuncSetAttribute(attn_mma_kernel, cudaFuncAttributeMaxDynamicSharedMemorySize, ASMEM);
        attr_set = true;
    }

    const int M = B * E;                       // 8192
    const dim3 gQKV(12, M / 128);
    const dim3 gD(D / 128, M / 128);
    const dim3 gF(F / 128, M / 128);
    const dim3 tb(32, 8);

    transposeA_kernel<<<dim3(16, 16, 16), tb>>>(wq, wk, wv, wo, p_wH);
    transposeB_kernel<<<dim3(64, 16, 8), tb>>>(w1, w2, p_wH);
    build_events_kernel<<<B, 256>>>(x, p_rows, p_mask);
    proj_kernel<<<M / 32, 256>>>(p_rows, proj_w, proj_b, p_h);

    for (int l = 0; l < NL; l++) {
        const size_t oQ = OFF_QKV + (size_t)l * 3 * D * D;
        const size_t oO = OFF_OT  + (size_t)l * D * D;
        const size_t o1 = OFF_W1T + (size_t)l * D * F;
        const size_t o2 = OFF_W2T + (size_t)l * D * F;

        ln_kernel<<<M / 8, 256>>>(p_h, ln1_g + l * D, ln1_b + l * D, p_zh);
        tgemm_kernel<0, 0, 0, 2><<<gQKV, 128, GSMEM>>>(
            p_zh, p_wH + oQ, nullptr, p_qh, p_kh, p_vh, M, 3 * D, D);
        attn_mma_kernel<<<dim3(E / 64, NH, B), 128, ASMEM>>>(
            p_qh, p_kh, p_vh, p_mask, p_oh);
        tgemm_kernel<0, 0, 1, 0><<<gD, 128, GSMEM>>>(
            p_oh, p_wH + oO, nullptr, p_h, nullptr, nullptr, M, D, D);

        ln_kernel<<<M / 8, 256>>>(p_h, ln2_g + l * D, ln2_b + l * D, p_zh);
        tgemm_kernel<1, 1, 0, 1><<<gF, 128, GSMEM>>>(
            p_zh, p_wH + o1, b1 + (size_t)l * F, p_fh, nullptr, nullptr, M, F, D);
        tgemm_kernel<1, 0, 1, 0><<<gD, 128, GSMEM>>>(
            p_fh, p_wH + o2, b2 + (size_t)l * D, p_h, nullptr, nullptr, M, D, F);
    }

    lnpool1_kernel<<<dim3(16, B), 256>>>(p_h, lnf_g, lnf_b, p_mask, p_pool, p_pcnt);
    lnpool2_kernel<<<B, D>>>(p_pool, p_pcnt, out);
}